// round 8
// baseline (speedup 1.0000x reference)
#include <cuda_runtime.h>
#include <cstdint>

typedef unsigned long long u64;

#define GB 16
#define NB 2048
#define NGRP (NB/GB)     // 128 groups
#define NCTA (NGRP*2)    // 256 CTAs (128 clusters of 2)
#define VMAXD 128
#define HS 20            // h_s row stride (floats): 80B, 16B-aligned rows
#define CS 17            // c_s row stride

// ---------------- device scratch ----------------
__device__ __align__(16) float g_Wih1g[15*1024];
__device__ __align__(16) float g_Whh1g[256*1024];
__device__ __align__(16) float g_b1c[1024];
__device__ __align__(16) float g_Wih2g[256*1024];
__device__ __align__(16) float g_Whh2g[256*1024];
__device__ __align__(16) float g_b2c[1024];
__device__ __align__(16) float g_W1T[256*1024];
__device__ __align__(16) float g_W2T[1024*1024];
__device__ __align__(16) float g_W3T[1024*512];
__device__ __align__(16) float g_W4T[512*256];
__device__ __align__(16) float g_henc[NB*256];
__device__ __align__(16) float g_x1[NB*1024];
__device__ __align__(16) float g_x2[NB*1024];
__device__ __align__(16) float g_x3[NB*512];
__device__ __align__(16) float g_x4[NB*256];
__device__ __align__(16) float g_decin[NB*1024];
__device__ int   g_order[NB];

// ---------------- helpers ----------------
__device__ __forceinline__ u64 pk2(float x, float y){
    u64 r; asm("mov.b64 %0,{%1,%2};" : "=l"(r) : "f"(x), "f"(y)); return r;
}
__device__ __forceinline__ float2 upk2(u64 v){
    float2 r; asm("mov.b64 {%0,%1},%2;" : "=f"(r.x), "=f"(r.y) : "l"(v)); return r;
}
__device__ __forceinline__ void fma2(u64& d, u64 a, u64 b){
    asm("fma.rn.f32x2 %0,%1,%2,%0;" : "+l"(d) : "l"(a), "l"(b));
}
__device__ __forceinline__ float sigf(float x){ return 1.0f/(1.0f + __expf(-x)); }
__device__ __forceinline__ float tanhfast(float x){ return 2.0f*sigf(2.0f*x) - 1.0f; }

__device__ __forceinline__ uint32_t s2u(const void* p){
    uint32_t a;
    asm("{ .reg .u64 t; cvta.to.shared.u64 t,%1; cvt.u32.u64 %0,t; }" : "=r"(a) : "l"(p));
    return a;
}
__device__ __forceinline__ uint32_t mapa_u32(uint32_t a, uint32_t trank){
    uint32_t d; asm("mapa.shared::cluster.u32 %0,%1,%2;" : "=r"(d) : "r"(a), "r"(trank));
    return d;
}
__device__ __forceinline__ void st_cl_f4(uint32_t addr, float4 v){
    asm volatile("st.shared::cluster.v4.b32 [%0],{%1,%2,%3,%4};"
        :: "r"(addr), "r"(__float_as_uint(v.x)), "r"(__float_as_uint(v.y)),
           "r"(__float_as_uint(v.z)), "r"(__float_as_uint(v.w)) : "memory");
}
__device__ __forceinline__ void st_cl_f1(uint32_t addr, float v){
    asm volatile("st.shared::cluster.b32 [%0],%1;" :: "r"(addr), "r"(__float_as_uint(v)) : "memory");
}
#define CLUSTER_SYNC() do{ \
    asm volatile("barrier.cluster.arrive.aligned;" ::: "memory"); \
    asm volatile("barrier.cluster.wait.aligned;" ::: "memory"); }while(0)

// ---------------- weight prep ----------------
__global__ void k_prep_gates(const float* __restrict__ Whh1,
                             const float* __restrict__ Wih2,
                             const float* __restrict__ Whh2){
    int idx = blockIdx.x*blockDim.x + threadIdx.x;
    int m = idx >> 18;
    int r = idx & 262143;
    int k = r >> 10; int n = r & 1023; int jj = n >> 2, g = n & 3;
    int src = (g*256 + jj)*256 + k;
    if (m == 0)      g_Whh1g[r] = Whh1[src];
    else if (m == 1) g_Wih2g[r] = Wih2[src];
    else             g_Whh2g[r] = Whh2[src];
}

__global__ void k_prep_small(const float* __restrict__ Wih1,
                             const float* __restrict__ bih1, const float* __restrict__ bhh1,
                             const float* __restrict__ bih2, const float* __restrict__ bhh2){
    int idx = blockIdx.x*blockDim.x + threadIdx.x;
    if (idx < 15360){
        int k = idx >> 10, n = idx & 1023, jj = n >> 2, g = n & 3;
        g_Wih1g[idx] = Wih1[(g*256 + jj)*15 + k];
    } else if (idx < 16384){
        int n = idx - 15360; int jj = n >> 2, g = n & 3;
        g_b1c[n] = bih1[g*256 + jj] + bhh1[g*256 + jj];
    } else if (idx < 17408){
        int n = idx - 16384; int jj = n >> 2, g = n & 3;
        g_b2c[n] = bih2[g*256 + jj] + bhh2[g*256 + jj];
    }
}

__global__ void k_prep_T(const float* __restrict__ W1, const float* __restrict__ W2,
                         const float* __restrict__ W3, const float* __restrict__ W4){
    int idx = blockIdx.x*blockDim.x + threadIdx.x;
    if (idx < 262144){
        int k = idx >> 10, n = idx & 1023; g_W1T[idx] = W1[n*256 + k];
    } else if (idx < 1310720){
        int r = idx - 262144; int k = r >> 10, n = r & 1023; g_W2T[r] = W2[n*1024 + k];
    } else if (idx < 1835008){
        int r = idx - 1310720; int k = r >> 9, n = r & 511; g_W3T[r] = W3[n*1024 + k];
    } else if (idx < 1966080){
        int r = idx - 1835008; int k = r >> 8, n = r & 255; g_W4T[r] = W4[n*512 + k];
    }
}

// ---------------- single-launch length sort (descending) ----------------
__global__ void k_sort(const int* __restrict__ lengths){
    __shared__ int hist[129];
    __shared__ int start[129];
    int tid = threadIdx.x;
    if (tid < 129) hist[tid] = 0;
    __syncthreads();
    for (int b = tid; b < NB; b += 256) atomicAdd(&hist[lengths[b]], 1);
    __syncthreads();
    if (tid == 0){
        int run = 0;
        for (int l = 128; l >= 1; l--){ start[l] = run; run += hist[l]; }
    }
    __syncthreads();
    for (int b = tid; b < NB; b += 256){
        int l = lengths[b];
        int p = atomicAdd(&start[l], 1);
        g_order[p] = b;
    }
}

// ---------------- encoder LSTM: cluster-2, gate-split, GB=16 ----------------
__global__ __launch_bounds__(256, 2) __cluster_dims__(2, 1, 1)
void k_encoder(const float* __restrict__ state, const int* __restrict__ lengths){
    __shared__ int s_b[GB]; __shared__ int s_len[GB]; __shared__ int s_maxs;
    __shared__ __align__(16) float h_s[2][256][HS];   // mirrored full h
    __shared__ __align__(16) float x_s[2][15][16];    // [buf][e][b]
    const int tid  = threadIdx.x;
    const int rank = blockIdx.x & 1;
    const int grp  = blockIdx.x >> 1;

    if (tid < GB){ int b = g_order[grp*GB + tid]; s_b[tid] = b; s_len[tid] = lengths[b]; }
    for (int i = tid; i < 2*256*HS; i += 256) ((float*)h_s)[i] = 0.0f;  // zero both bufs
    __syncthreads();
    if (tid == 0){
        int m = 1;
        #pragma unroll
        for (int i = 0; i < GB; i++) m = max(m, s_len[i]);
        s_maxs = m;
    }
    if (tid < 240){ int bb = tid/15, e = tid - 15*bb; x_s[0][e][bb] = state[(s_b[bb]*VMAXD + 0)*15 + e]; }
    __syncthreads();
    const int T = s_maxs;

    const int u    = tid >> 1;          // local hidden unit 0..127
    const int half = tid & 1;
    const int ug   = rank*128 + u;      // global hidden unit
    const int b0   = half*8;            // my batch lanes b0..b0+7
    const int col  = ug << 2;           // weight/bias column base

    const float4 bv = *(const float4*)(g_b1c + col);
    const u64 bi0 = pk2(bv.x,bv.x), bi1 = pk2(bv.y,bv.y), bi2 = pk2(bv.z,bv.z), bi3 = pk2(bv.w,bv.w);

    float cr[8], hreg[8];
    #pragma unroll
    for (int i = 0; i < 8; i++){ cr[i] = 0.0f; hreg[i] = 0.0f; }

    // remote h row addresses for both buffers
    uint32_t la0 = s2u(&h_s[0][ug][b0]);
    uint32_t la1 = s2u(&h_s[1][ug][b0]);
    uint32_t ra0 = mapa_u32(la0, rank ^ 1);
    uint32_t ra1 = mapa_u32(la1, rank ^ 1);

    CLUSTER_SYNC();

    for (int t = 0; t < T; t++){
        const int cb = t & 1, nb = cb ^ 1;
        u64 acc[4][4];
        #pragma unroll
        for (int bp = 0; bp < 4; bp++){ acc[bp][0]=bi0; acc[bp][1]=bi1; acc[bp][2]=bi2; acc[bp][3]=bi3; }

        #pragma unroll
        for (int k = 0; k < 15; k++){
            float4 w = *(const float4*)(g_Wih1g + (k<<10) + col);
            u64 w0 = pk2(w.x,w.x), w1 = pk2(w.y,w.y), w2 = pk2(w.z,w.z), w3 = pk2(w.w,w.w);
            const float* xr = &x_s[cb][k][b0];
            #pragma unroll
            for (int bp = 0; bp < 4; bp++){
                u64 xp = *(const u64*)(xr + 2*bp);
                fma2(acc[bp][0], w0, xp); fma2(acc[bp][1], w1, xp);
                fma2(acc[bp][2], w2, xp); fma2(acc[bp][3], w3, xp);
            }
        }
        #pragma unroll 4
        for (int k = 0; k < 256; k++){
            float4 w = *(const float4*)(g_Whh1g + (k<<10) + col);
            u64 w0 = pk2(w.x,w.x), w1 = pk2(w.y,w.y), w2 = pk2(w.z,w.z), w3 = pk2(w.w,w.w);
            const float* hr = &h_s[cb][k][b0];
            #pragma unroll
            for (int bp = 0; bp < 4; bp++){
                u64 hp = *(const u64*)(hr + 2*bp);
                fma2(acc[bp][0], w0, hp); fma2(acc[bp][1], w1, hp);
                fma2(acc[bp][2], w2, hp); fma2(acc[bp][3], w3, hp);
            }
        }

        // prefetch next x (local double buffer)
        if (tid < 240 && t + 1 < T){
            int bb = tid/15, e = tid - 15*bb;
            x_s[nb][e][bb] = state[(s_b[bb]*VMAXD + (t+1))*15 + e];
        }

        // gate nonlinearity + masked state update (registers)
        #pragma unroll
        for (int bp = 0; bp < 4; bp++){
            float2 gi = upk2(acc[bp][0]), gf = upk2(acc[bp][1]);
            float2 gg = upk2(acc[bp][2]), go = upk2(acc[bp][3]);
            int l = 2*bp;
            if (t < s_len[b0 + l]){
                float cn = sigf(gf.x)*cr[l] + sigf(gi.x)*tanhfast(gg.x);
                cr[l] = cn; hreg[l] = sigf(go.x)*tanhfast(cn);
            }
            l++;
            if (t < s_len[b0 + l]){
                float cn = sigf(gf.y)*cr[l] + sigf(gi.y)*tanhfast(gg.y);
                cr[l] = cn; hreg[l] = sigf(go.y)*tanhfast(cn);
            }
        }

        // publish h to next buffer: local + peer (DSMEM); rows are 16B-aligned (HS=20)
        float4 h0 = make_float4(hreg[0], hreg[1], hreg[2], hreg[3]);
        float4 h1 = make_float4(hreg[4], hreg[5], hreg[6], hreg[7]);
        float* ld = &h_s[nb][ug][b0];
        *(float4*)(ld)     = h0;
        *(float4*)(ld + 4) = h1;
        uint32_t ra = nb ? ra1 : ra0;
        st_cl_f4(ra,      h0);
        st_cl_f4(ra + 16, h1);

        CLUSTER_SYNC();   // h writes visible cluster-wide; next step reads buffer nb
    }

    #pragma unroll
    for (int i = 0; i < 8; i++) g_henc[s_b[b0 + i]*256 + ug] = hreg[i];
}

// ---------------- row GEMM: C = act(A @ W^T + bias), 8 rows / CTA ----------------
__global__ __launch_bounds__(256, 2)
void k_rowgemm(int layer, const float* __restrict__ bias_in){
    const float *A, *W; float* C; int K, N; bool dorelu = true; const float* bias = bias_in;
    if      (layer == 0){ A = g_henc; W = g_W1T;   C = g_x1;    K = 256;  N = 1024; }
    else if (layer == 1){ A = g_x1;   W = g_W2T;   C = g_x2;    K = 1024; N = 1024; }
    else if (layer == 2){ A = g_x2;   W = g_W3T;   C = g_x3;    K = 1024; N = 512;  }
    else if (layer == 3){ A = g_x3;   W = g_W4T;   C = g_x4;    K = 512;  N = 256;  }
    else               { A = g_x4;   W = g_Wih2g; C = g_decin; K = 256;  N = 1024; dorelu = false; bias = g_b2c; }

    __shared__ __align__(16) float A_s[1024*8];
    const int tid = threadIdx.x;
    const int row0 = blockIdx.x * 8;
    for (int idx = tid; idx < 8*K; idx += 256){
        int i = idx / K, k = idx - i*K;
        A_s[k*8 + i] = A[(row0 + i)*K + k];
    }
    __syncthreads();

    const int j = tid;
    if (4*j < N){
        float4 bvv = *(const float4*)(bias + 4*j);
        u64 acc[4][4];
        u64 b0 = pk2(bvv.x,bvv.x), b1 = pk2(bvv.y,bvv.y), b2 = pk2(bvv.z,bvv.z), b3 = pk2(bvv.w,bvv.w);
        #pragma unroll
        for (int bp = 0; bp < 4; bp++){ acc[bp][0]=b0; acc[bp][1]=b1; acc[bp][2]=b2; acc[bp][3]=b3; }

        #pragma unroll 4
        for (int k = 0; k < K; k++){
            float4 w = *(const float4*)(W + k*N + 4*j);
            u64 w0 = pk2(w.x,w.x), w1 = pk2(w.y,w.y), w2 = pk2(w.z,w.z), w3 = pk2(w.w,w.w);
            const float* ar = A_s + k*8;
            #pragma unroll
            for (int bp = 0; bp < 4; bp++){
                u64 ap = *(const u64*)(ar + 2*bp);
                fma2(acc[bp][0], w0, ap); fma2(acc[bp][1], w1, ap);
                fma2(acc[bp][2], w2, ap); fma2(acc[bp][3], w3, ap);
            }
        }
        #pragma unroll
        for (int bp = 0; bp < 4; bp++){
            float2 v0 = upk2(acc[bp][0]), v1 = upk2(acc[bp][1]);
            float2 v2 = upk2(acc[bp][2]), v3 = upk2(acc[bp][3]);
            float4 r0 = make_float4(v0.x, v1.x, v2.x, v3.x);
            float4 r1 = make_float4(v0.y, v1.y, v2.y, v3.y);
            if (dorelu){
                r0.x = fmaxf(r0.x,0.f); r0.y = fmaxf(r0.y,0.f); r0.z = fmaxf(r0.z,0.f); r0.w = fmaxf(r0.w,0.f);
                r1.x = fmaxf(r1.x,0.f); r1.y = fmaxf(r1.y,0.f); r1.z = fmaxf(r1.z,0.f); r1.w = fmaxf(r1.w,0.f);
            }
            *(float4*)(C + (row0 + 2*bp    )*N + 4*j) = r0;
            *(float4*)(C + (row0 + 2*bp + 1)*N + 4*j) = r1;
        }
    }
}

// ---------------- decoder LSTM + policy head: cluster-2, gate-split, GB=16 ----------------
// h_s + c_s live in DYNAMIC shared memory (49,664 B) to stay under the 48KB static cap.
#define DEC_DYN_BYTES ((2*256*HS + 128*CS)*4)

__global__ __launch_bounds__(256, 2) __cluster_dims__(2, 1, 1)
void k_decoder(const int* __restrict__ lengths, const float* __restrict__ Wpi,
               const float* __restrict__ bpi, float* __restrict__ out){
    extern __shared__ __align__(16) float dyn[];
    float (*h_s)[256][HS] = (float(*)[256][HS])dyn;          // 2*256*HS floats
    float (*c_s)[CS]      = (float(*)[CS])(dyn + 2*256*HS);  // 128*CS floats

    __shared__ int s_b[GB]; __shared__ int s_len[GB]; __shared__ int s_maxs;
    __shared__ float wpi_s[512];
    __shared__ float p_s[2][32];                     // [rank][b*2+a] partial sums
    __shared__ float bpi_s[2];
    const int tid  = threadIdx.x;
    const int rank = blockIdx.x & 1;
    const int grp  = blockIdx.x >> 1;

    if (tid < GB){ int b = g_order[grp*GB + tid]; s_b[tid] = b; s_len[tid] = lengths[b]; }
    for (int i = tid; i < 2*256*HS; i += 256) dyn[i] = 0.0f;
    if (tid < 2) bpi_s[tid] = bpi[tid];
    for (int i = tid; i < 512; i += 256) wpi_s[i] = Wpi[i];
    __syncthreads();
    if (tid == 0){
        int m = 1;
        #pragma unroll
        for (int i = 0; i < GB; i++) m = max(m, s_len[i]);
        s_maxs = m;
    }
    __syncthreads();
    const int T = s_maxs;

    const int u    = tid >> 1;
    const int half = tid & 1;
    const int ug   = rank*128 + u;
    const int b0   = half*8;
    const int col  = ug << 2;

    // decoder constant input gates (registers): din[g][bp] packs lanes (b0+2bp, b0+2bp+1)
    u64 din[4][4];
    #pragma unroll
    for (int g = 0; g < 4; g++){
        float v[8];
        #pragma unroll
        for (int i = 0; i < 8; i++) v[i] = g_decin[s_b[b0 + i]*1024 + col + g];
        #pragma unroll
        for (int bp = 0; bp < 4; bp++) din[g][bp] = pk2(v[2*bp], v[2*bp+1]);
    }
    float cr[8];
    #pragma unroll
    for (int i = 0; i < 8; i++) cr[i] = 0.0f;

    uint32_t la0 = s2u(&h_s[0][ug][b0]);
    uint32_t la1 = s2u(&h_s[1][ug][b0]);
    uint32_t ra0 = mapa_u32(la0, rank ^ 1);
    uint32_t ra1 = mapa_u32(la1, rank ^ 1);

    CLUSTER_SYNC();

    for (int t = 0; t < T; t++){
        const int cb = t & 1, nb = cb ^ 1;

        // write output of previous step (p_s is stable until this step's partial write)
        if (t > 0 && tid < 32){
            int b = tid >> 1, a = tid & 1;
            if (t - 1 < s_len[b]){
                float v = tanhfast(p_s[0][tid] + p_s[1][tid] + bpi_s[a]);
                out[(s_b[b]*VMAXD + (t-1))*2 + a] = v;
            }
        }

        u64 acc[4][4];
        #pragma unroll
        for (int bp = 0; bp < 4; bp++){
            acc[bp][0] = din[0][bp]; acc[bp][1] = din[1][bp];
            acc[bp][2] = din[2][bp]; acc[bp][3] = din[3][bp];
        }
        #pragma unroll 4
        for (int k = 0; k < 256; k++){
            float4 w = *(const float4*)(g_Whh2g + (k<<10) + col);
            u64 w0 = pk2(w.x,w.x), w1 = pk2(w.y,w.y), w2 = pk2(w.z,w.z), w3 = pk2(w.w,w.w);
            const float* hr = &h_s[cb][k][b0];
            #pragma unroll
            for (int bp = 0; bp < 4; bp++){
                u64 hp = *(const u64*)(hr + 2*bp);
                fma2(acc[bp][0], w0, hp); fma2(acc[bp][1], w1, hp);
                fma2(acc[bp][2], w2, hp); fma2(acc[bp][3], w3, hp);
            }
        }

        float hreg[8];
        #pragma unroll
        for (int bp = 0; bp < 4; bp++){
            float2 gi = upk2(acc[bp][0]), gf = upk2(acc[bp][1]);
            float2 gg = upk2(acc[bp][2]), go = upk2(acc[bp][3]);
            int l = 2*bp;
            {
                float cn = sigf(gf.x)*cr[l] + sigf(gi.x)*tanhfast(gg.x);
                cr[l] = cn; hreg[l] = sigf(go.x)*tanhfast(cn);
            }
            l++;
            {
                float cn = sigf(gf.y)*cr[l] + sigf(gi.y)*tanhfast(gg.y);
                cr[l] = cn; hreg[l] = sigf(go.y)*tanhfast(cn);
            }
        }

        // publish h (local + peer), stash c locally for the policy head
        float4 h0 = make_float4(hreg[0], hreg[1], hreg[2], hreg[3]);
        float4 h1 = make_float4(hreg[4], hreg[5], hreg[6], hreg[7]);
        float* ld = &h_s[nb][ug][b0];
        *(float4*)(ld)     = h0;
        *(float4*)(ld + 4) = h1;
        uint32_t ra = nb ? ra1 : ra0;
        st_cl_f4(ra,      h0);
        st_cl_f4(ra + 16, h1);
        #pragma unroll
        for (int i = 0; i < 8; i++) c_s[u][b0 + i] = cr[i];

        __syncthreads();   // c_s complete before reduction reads

        // policy head partials over MY 128 units: 32 dots (16 b x 2 a), 8 lanes each
        {
            int p = tid >> 3, kk = tid & 7;
            int b = p >> 1, a = p & 1;
            const float* wr = wpi_s + a*256 + rank*128;
            float sum = 0.0f;
            #pragma unroll
            for (int q = 0; q < 16; q++){
                int uu = kk + 8*q;
                sum += c_s[uu][b] * wr[uu];
            }
            sum += __shfl_xor_sync(0xffffffffu, sum, 4);
            sum += __shfl_xor_sync(0xffffffffu, sum, 2);
            sum += __shfl_xor_sync(0xffffffffu, sum, 1);
            if (kk == 0){
                p_s[rank][p] = sum;
                st_cl_f1(mapa_u32(s2u(&p_s[rank][p]), rank ^ 1), sum);
            }
        }

        CLUSTER_SYNC();
    }

    // final step's output
    if (tid < 32){
        int b = tid >> 1, a = tid & 1;
        if (T - 1 < s_len[b]){
            float v = tanhfast(p_s[0][tid] + p_s[1][tid] + bpi_s[a]);
            out[(s_b[b]*VMAXD + (T-1))*2 + a] = v;
        }
    }
}

__global__ void k_zero_out(float4* out){
    int i = blockIdx.x*blockDim.x + threadIdx.x;
    if (i < 131072) out[i] = make_float4(0.f, 0.f, 0.f, 0.f);
}

// ---------------- launch ----------------
extern "C" void kernel_launch(void* const* d_in, const int* in_sizes, int n_in,
                              void* d_out, int out_size){
    const float* state = (const float*)d_in[0];
    const int*   lengths = (const int*)d_in[1];
    const float* Wih1 = (const float*)d_in[2];
    const float* Whh1 = (const float*)d_in[3];
    const float* bih1 = (const float*)d_in[4];
    const float* bhh1 = (const float*)d_in[5];
    const float* W1 = (const float*)d_in[6];
    const float* b1 = (const float*)d_in[7];
    const float* W2 = (const float*)d_in[8];
    const float* b2 = (const float*)d_in[9];
    const float* W3 = (const float*)d_in[10];
    const float* b3 = (const float*)d_in[11];
    const float* W4 = (const float*)d_in[12];
    const float* b4 = (const float*)d_in[13];
    const float* Wih2 = (const float*)d_in[14];
    const float* Whh2 = (const float*)d_in[15];
    const float* bih2 = (const float*)d_in[16];
    const float* bhh2 = (const float*)d_in[17];
    const float* Wpi = (const float*)d_in[18];
    const float* bpi = (const float*)d_in[19];
    float* out = (float*)d_out;
    (void)b4;

    cudaFuncSetAttribute(k_decoder, cudaFuncAttributeMaxDynamicSharedMemorySize, DEC_DYN_BYTES);

    k_sort<<<1, 256>>>(lengths);
    k_prep_gates<<<3072, 256>>>(Whh1, Wih2, Whh2);
    k_prep_small<<<68, 256>>>(Wih1, bih1, bhh1, bih2, bhh2);
    k_prep_T<<<7680, 256>>>(W1, W2, W3, W4);

    k_encoder<<<NCTA, 256>>>(state, lengths);

    k_rowgemm<<<NB/8, 256>>>(0, b1);
    k_rowgemm<<<NB/8, 256>>>(1, b2);
    k_rowgemm<<<NB/8, 256>>>(2, b3);
    k_rowgemm<<<NB/8, 256>>>(3, b4);
    k_rowgemm<<<NB/8, 256>>>(4, b1);   // layer 4 uses g_b2c internally

    k_zero_out<<<512, 256>>>((float4*)out);
    k_decoder<<<NCTA, 256, DEC_DYN_BYTES>>>(lengths, Wpi, bpi, out);
}

// round 9
// speedup vs baseline: 1.1241x; 1.1241x over previous
#include <cuda_runtime.h>
#include <cstdint>

typedef unsigned long long u64;

#define BC 8
#define NB 2048
#define NG (NB/BC)       // 256 groups == 256 CTAs
#define VMAXD 128
#define HS 12            // h_s row stride: 48B rows, 16B-aligned

// ---------------- device scratch ----------------
__device__ __align__(16) float g_Wih1g[15*1024];
__device__ __align__(16) float g_Whh1g[256*1024];
__device__ __align__(16) float g_b1c[1024];
__device__ __align__(16) float g_Wih2g[256*1024];
__device__ __align__(16) float g_Whh2g[256*1024];
__device__ __align__(16) float g_b2c[1024];
__device__ __align__(16) float g_W1T[256*1024];
__device__ __align__(16) float g_W2T[1024*1024];
__device__ __align__(16) float g_W3T[1024*512];
__device__ __align__(16) float g_W4T[512*256];
__device__ __align__(16) float g_henc[NB*256];
__device__ __align__(16) float g_x1[NB*1024];
__device__ __align__(16) float g_x2[NB*1024];
__device__ __align__(16) float g_x3[NB*512];
__device__ __align__(16) float g_x4[NB*256];
__device__ __align__(16) float g_decin[NB*1024];
__device__ int   g_order[NB];

// ---------------- helpers ----------------
__device__ __forceinline__ u64 pk2(float x, float y){
    u64 r; asm("mov.b64 %0,{%1,%2};" : "=l"(r) : "f"(x), "f"(y)); return r;
}
__device__ __forceinline__ float2 upk2(u64 v){
    float2 r; asm("mov.b64 {%0,%1},%2;" : "=f"(r.x), "=f"(r.y) : "l"(v)); return r;
}
__device__ __forceinline__ void fma2(u64& d, u64 a, u64 b){
    asm("fma.rn.f32x2 %0,%1,%2,%0;" : "+l"(d) : "l"(a), "l"(b));
}
__device__ __forceinline__ float sigf(float x){ return 1.0f/(1.0f + __expf(-x)); }
__device__ __forceinline__ float tanhfast(float x){ return 2.0f*sigf(2.0f*x) - 1.0f; }

// Load-balanced CTA->group rank map, exploiting SM(bid)==SM(bid+148) for
// classic placement LUT[bid%148]:
//   bids 108..147 (solo SMs)        -> ranks 0..39   (the 40 longest groups)
//   pairs (b, b+148), b in [0,108)  -> ranks 40+b and 255-b (length sums ~const)
__device__ __forceinline__ int grp_of(int bid){
    return (bid >= 148) ? (403 - bid) : (bid >= 108 ? bid - 108 : bid + 40);
}

// ---------------- weight prep ----------------
__global__ void k_prep_gates(const float* __restrict__ Whh1,
                             const float* __restrict__ Wih2,
                             const float* __restrict__ Whh2){
    int idx = blockIdx.x*blockDim.x + threadIdx.x;
    int m = idx >> 18;
    int r = idx & 262143;
    int k = r >> 10; int n = r & 1023; int jj = n >> 2, g = n & 3;
    int src = (g*256 + jj)*256 + k;
    if (m == 0)      g_Whh1g[r] = Whh1[src];
    else if (m == 1) g_Wih2g[r] = Wih2[src];
    else             g_Whh2g[r] = Whh2[src];
}

__global__ void k_prep_small(const float* __restrict__ Wih1,
                             const float* __restrict__ bih1, const float* __restrict__ bhh1,
                             const float* __restrict__ bih2, const float* __restrict__ bhh2){
    int idx = blockIdx.x*blockDim.x + threadIdx.x;
    if (idx < 15360){
        int k = idx >> 10, n = idx & 1023, jj = n >> 2, g = n & 3;
        g_Wih1g[idx] = Wih1[(g*256 + jj)*15 + k];
    } else if (idx < 16384){
        int n = idx - 15360; int jj = n >> 2, g = n & 3;
        g_b1c[n] = bih1[g*256 + jj] + bhh1[g*256 + jj];
    } else if (idx < 17408){
        int n = idx - 16384; int jj = n >> 2, g = n & 3;
        g_b2c[n] = bih2[g*256 + jj] + bhh2[g*256 + jj];
    }
}

__global__ void k_prep_T(const float* __restrict__ W1, const float* __restrict__ W2,
                         const float* __restrict__ W3, const float* __restrict__ W4){
    int idx = blockIdx.x*blockDim.x + threadIdx.x;
    if (idx < 262144){
        int k = idx >> 10, n = idx & 1023; g_W1T[idx] = W1[n*256 + k];
    } else if (idx < 1310720){
        int r = idx - 262144; int k = r >> 10, n = r & 1023; g_W2T[r] = W2[n*1024 + k];
    } else if (idx < 1835008){
        int r = idx - 1310720; int k = r >> 9, n = r & 511; g_W3T[r] = W3[n*1024 + k];
    } else if (idx < 1966080){
        int r = idx - 1835008; int k = r >> 8, n = r & 255; g_W4T[r] = W4[n*512 + k];
    }
}

// ---------------- single-launch length sort (descending) ----------------
__global__ void k_sort(const int* __restrict__ lengths){
    __shared__ int hist[129];
    __shared__ int start[129];
    int tid = threadIdx.x;
    if (tid < 129) hist[tid] = 0;
    __syncthreads();
    for (int b = tid; b < NB; b += 256) atomicAdd(&hist[lengths[b]], 1);
    __syncthreads();
    if (tid == 0){
        int run = 0;
        for (int l = 128; l >= 1; l--){ start[l] = run; run += hist[l]; }
    }
    __syncthreads();
    for (int b = tid; b < NB; b += 256){
        int l = lengths[b];
        int p = atomicAdd(&start[l], 1);
        g_order[p] = b;
    }
}

// ---------------- encoder LSTM: BC=8, balanced groups, double-buffered h ----------------
__global__ __launch_bounds__(256, 2)
void k_encoder(const float* __restrict__ state, const int* __restrict__ lengths){
    __shared__ int s_b[BC]; __shared__ int s_len[BC]; __shared__ int s_maxs;
    __shared__ __align__(16) float h_s[2][256][HS];
    __shared__ __align__(16) float x_s[2][15][8];
    const int tid = threadIdx.x;
    const int grp = grp_of(blockIdx.x);

    if (tid < BC){ int b = g_order[grp*BC + tid]; s_b[tid] = b; s_len[tid] = lengths[b]; }
    for (int i = tid; i < 2*256*HS; i += 256) ((float*)h_s)[i] = 0.0f;
    __syncthreads();
    if (tid == 0){
        int m = 1;
        #pragma unroll
        for (int i = 0; i < BC; i++) m = max(m, s_len[i]);
        s_maxs = m;
    }
    if (tid < 120){ int i = tid/15, e = tid - 15*i; x_s[0][e][i] = state[(s_b[i]*VMAXD + 0)*15 + e]; }
    __syncthreads();
    const int T = s_maxs;

    const int j = tid;
    const int col = j << 2;
    const float4 bv = *(const float4*)(g_b1c + col);
    const u64 bi0 = pk2(bv.x,bv.x), bi1 = pk2(bv.y,bv.y), bi2 = pk2(bv.z,bv.z), bi3 = pk2(bv.w,bv.w);

    float cr[BC], hreg[BC];
    #pragma unroll
    for (int i = 0; i < BC; i++){ cr[i] = 0.0f; hreg[i] = 0.0f; }

    for (int t = 0; t < T; t++){
        const int cb = t & 1, nb = cb ^ 1;
        u64 acc[4][4];
        #pragma unroll
        for (int bp = 0; bp < 4; bp++){ acc[bp][0]=bi0; acc[bp][1]=bi1; acc[bp][2]=bi2; acc[bp][3]=bi3; }

        #pragma unroll
        for (int k = 0; k < 15; k++){
            float4 w = *(const float4*)(g_Wih1g + (k<<10) + col);
            u64 w0 = pk2(w.x,w.x), w1 = pk2(w.y,w.y), w2 = pk2(w.z,w.z), w3 = pk2(w.w,w.w);
            const float* xr = &x_s[cb][k][0];
            #pragma unroll
            for (int bp = 0; bp < 4; bp++){
                u64 xp = *(const u64*)(xr + 2*bp);
                fma2(acc[bp][0], w0, xp); fma2(acc[bp][1], w1, xp);
                fma2(acc[bp][2], w2, xp); fma2(acc[bp][3], w3, xp);
            }
        }
        #pragma unroll 4
        for (int k = 0; k < 256; k++){
            float4 w = *(const float4*)(g_Whh1g + (k<<10) + col);
            u64 w0 = pk2(w.x,w.x), w1 = pk2(w.y,w.y), w2 = pk2(w.z,w.z), w3 = pk2(w.w,w.w);
            const float* hr = &h_s[cb][k][0];
            #pragma unroll
            for (int bp = 0; bp < 4; bp++){
                u64 hp = *(const u64*)(hr + 2*bp);
                fma2(acc[bp][0], w0, hp); fma2(acc[bp][1], w1, hp);
                fma2(acc[bp][2], w2, hp); fma2(acc[bp][3], w3, hp);
            }
        }

        // prefetch next x into the other buffer
        if (tid < 120 && t + 1 < T){
            int i = tid/15, e = tid - 15*i;
            x_s[nb][e][i] = state[(s_b[i]*VMAXD + (t+1))*15 + e];
        }

        // masked state update in registers
        #pragma unroll
        for (int bp = 0; bp < 4; bp++){
            float2 gi = upk2(acc[bp][0]), gf = upk2(acc[bp][1]);
            float2 gg = upk2(acc[bp][2]), go = upk2(acc[bp][3]);
            int l = 2*bp;
            if (t < s_len[l]){
                float cn = sigf(gf.x)*cr[l] + sigf(gi.x)*tanhfast(gg.x);
                cr[l] = cn; hreg[l] = sigf(go.x)*tanhfast(cn);
            }
            l++;
            if (t < s_len[l]){
                float cn = sigf(gf.y)*cr[l] + sigf(gi.y)*tanhfast(gg.y);
                cr[l] = cn; hreg[l] = sigf(go.y)*tanhfast(cn);
            }
        }

        // publish full h (unconditional; masked lanes carry old value) to next buffer
        float* ld = &h_s[nb][j][0];
        *(float4*)(ld)     = make_float4(hreg[0], hreg[1], hreg[2], hreg[3]);
        *(float4*)(ld + 4) = make_float4(hreg[4], hreg[5], hreg[6], hreg[7]);

        __syncthreads();   // single barrier per step (double-buffered h and x)
    }

    #pragma unroll
    for (int i = 0; i < BC; i++) g_henc[s_b[i]*256 + j] = hreg[i];
}

// ---------------- row GEMM: C = act(A @ W^T + bias), 8 rows / CTA ----------------
__global__ __launch_bounds__(256, 2)
void k_rowgemm(int layer, const float* __restrict__ bias_in){
    const float *A, *W; float* C; int K, N; bool dorelu = true; const float* bias = bias_in;
    if      (layer == 0){ A = g_henc; W = g_W1T;   C = g_x1;    K = 256;  N = 1024; }
    else if (layer == 1){ A = g_x1;   W = g_W2T;   C = g_x2;    K = 1024; N = 1024; }
    else if (layer == 2){ A = g_x2;   W = g_W3T;   C = g_x3;    K = 1024; N = 512;  }
    else if (layer == 3){ A = g_x3;   W = g_W4T;   C = g_x4;    K = 512;  N = 256;  }
    else               { A = g_x4;   W = g_Wih2g; C = g_decin; K = 256;  N = 1024; dorelu = false; bias = g_b2c; }

    __shared__ __align__(16) float A_s[1024*8];
    const int tid = threadIdx.x;
    const int row0 = blockIdx.x * 8;
    for (int idx = tid; idx < 8*K; idx += 256){
        int i = idx / K, k = idx - i*K;
        A_s[k*8 + i] = A[(row0 + i)*K + k];
    }
    __syncthreads();

    const int j = tid;
    if (4*j < N){
        float4 bvv = *(const float4*)(bias + 4*j);
        u64 acc[4][4];
        u64 b0 = pk2(bvv.x,bvv.x), b1 = pk2(bvv.y,bvv.y), b2 = pk2(bvv.z,bvv.z), b3 = pk2(bvv.w,bvv.w);
        #pragma unroll
        for (int bp = 0; bp < 4; bp++){ acc[bp][0]=b0; acc[bp][1]=b1; acc[bp][2]=b2; acc[bp][3]=b3; }

        #pragma unroll 4
        for (int k = 0; k < K; k++){
            float4 w = *(const float4*)(W + k*N + 4*j);
            u64 w0 = pk2(w.x,w.x), w1 = pk2(w.y,w.y), w2 = pk2(w.z,w.z), w3 = pk2(w.w,w.w);
            const float* ar = A_s + k*8;
            #pragma unroll
            for (int bp = 0; bp < 4; bp++){
                u64 ap = *(const u64*)(ar + 2*bp);
                fma2(acc[bp][0], w0, ap); fma2(acc[bp][1], w1, ap);
                fma2(acc[bp][2], w2, ap); fma2(acc[bp][3], w3, ap);
            }
        }
        #pragma unroll
        for (int bp = 0; bp < 4; bp++){
            float2 v0 = upk2(acc[bp][0]), v1 = upk2(acc[bp][1]);
            float2 v2 = upk2(acc[bp][2]), v3 = upk2(acc[bp][3]);
            float4 r0 = make_float4(v0.x, v1.x, v2.x, v3.x);
            float4 r1 = make_float4(v0.y, v1.y, v2.y, v3.y);
            if (dorelu){
                r0.x = fmaxf(r0.x,0.f); r0.y = fmaxf(r0.y,0.f); r0.z = fmaxf(r0.z,0.f); r0.w = fmaxf(r0.w,0.f);
                r1.x = fmaxf(r1.x,0.f); r1.y = fmaxf(r1.y,0.f); r1.z = fmaxf(r1.z,0.f); r1.w = fmaxf(r1.w,0.f);
            }
            *(float4*)(C + (row0 + 2*bp    )*N + 4*j) = r0;
            *(float4*)(C + (row0 + 2*bp + 1)*N + 4*j) = r1;
        }
    }
}

// ---------------- decoder LSTM + policy head: BC=8, balanced, din in registers ----------------
__global__ __launch_bounds__(256, 2)
void k_decoder(const int* __restrict__ lengths, const float* __restrict__ Wpi,
               const float* __restrict__ bpi, float* __restrict__ out){
    __shared__ int s_b[BC]; __shared__ int s_len[BC]; __shared__ int s_maxs;
    __shared__ __align__(16) float h_s[256][HS];   // single buffer, 2 syncs/step
    __shared__ __align__(16) float c_s[256*9];
    __shared__ float wpi_s[512]; __shared__ float bpi_s[2];
    const int tid = threadIdx.x;
    const int grp = grp_of(blockIdx.x);

    if (tid < BC){ int b = g_order[grp*BC + tid]; s_b[tid] = b; s_len[tid] = lengths[b]; }
    for (int i = tid; i < 256*HS; i += 256) ((float*)h_s)[i] = 0.0f;
    if (tid < 2) bpi_s[tid] = bpi[tid];
    for (int i = tid; i < 512; i += 256) wpi_s[i] = Wpi[i];
    __syncthreads();
    if (tid == 0){
        int m = 1;
        #pragma unroll
        for (int i = 0; i < BC; i++) m = max(m, s_len[i]);
        s_maxs = m;
    }

    const int j = tid;
    const int col = j << 2;

    // decoder constant input gates in registers
    u64 din[4][4];
    #pragma unroll
    for (int g = 0; g < 4; g++){
        float v[BC];
        #pragma unroll
        for (int i = 0; i < BC; i++) v[i] = g_decin[s_b[i]*1024 + col + g];
        #pragma unroll
        for (int bp = 0; bp < 4; bp++) din[g][bp] = pk2(v[2*bp], v[2*bp+1]);
    }
    float cr[BC];
    #pragma unroll
    for (int i = 0; i < BC; i++) cr[i] = 0.0f;
    __syncthreads();
    const int T = s_maxs;

    for (int t = 0; t < T; t++){
        u64 acc[4][4];
        #pragma unroll
        for (int bp = 0; bp < 4; bp++){
            acc[bp][0] = din[0][bp]; acc[bp][1] = din[1][bp];
            acc[bp][2] = din[2][bp]; acc[bp][3] = din[3][bp];
        }
        #pragma unroll 4
        for (int k = 0; k < 256; k++){
            float4 w = *(const float4*)(g_Whh2g + (k<<10) + col);
            u64 w0 = pk2(w.x,w.x), w1 = pk2(w.y,w.y), w2 = pk2(w.z,w.z), w3 = pk2(w.w,w.w);
            const float* hr = &h_s[k][0];
            #pragma unroll
            for (int bp = 0; bp < 4; bp++){
                u64 hp = *(const u64*)(hr + 2*bp);
                fma2(acc[bp][0], w0, hp); fma2(acc[bp][1], w1, hp);
                fma2(acc[bp][2], w2, hp); fma2(acc[bp][3], w3, hp);
            }
        }
        __syncthreads();   // all h reads complete before rewrite

        float hreg[BC];
        #pragma unroll
        for (int bp = 0; bp < 4; bp++){
            float2 gi = upk2(acc[bp][0]), gf = upk2(acc[bp][1]);
            float2 gg = upk2(acc[bp][2]), go = upk2(acc[bp][3]);
            int l = 2*bp;
            {
                float cn = sigf(gf.x)*cr[l] + sigf(gi.x)*tanhfast(gg.x);
                cr[l] = cn; hreg[l] = sigf(go.x)*tanhfast(cn);
            }
            l++;
            {
                float cn = sigf(gf.y)*cr[l] + sigf(gi.y)*tanhfast(gg.y);
                cr[l] = cn; hreg[l] = sigf(go.y)*tanhfast(cn);
            }
        }

        float* ld = &h_s[j][0];
        *(float4*)(ld)     = make_float4(hreg[0], hreg[1], hreg[2], hreg[3]);
        *(float4*)(ld + 4) = make_float4(hreg[4], hreg[5], hreg[6], hreg[7]);
        #pragma unroll
        for (int i = 0; i < BC; i++) c_s[j*9 + i] = cr[i];

        __syncthreads();   // h/c writes visible

        // policy head: 16 (b,a) dots over K=256, 16 lanes each
        {
            int p = tid >> 4, kk = tid & 15;
            int b = p >> 1, a = p & 1;
            const float* wr = wpi_s + a*256;
            float sum = 0.0f;
            #pragma unroll
            for (int q = 0; q < 16; q++){
                int k = kk + q*16;
                sum += c_s[k*9 + b] * wr[k];
            }
            sum += __shfl_xor_sync(0xffffffffu, sum, 8);
            sum += __shfl_xor_sync(0xffffffffu, sum, 4);
            sum += __shfl_xor_sync(0xffffffffu, sum, 2);
            sum += __shfl_xor_sync(0xffffffffu, sum, 1);
            if (kk == 0 && t < s_len[b])
                out[(s_b[b]*VMAXD + t)*2 + a] = tanhfast(sum + bpi_s[a]);
        }
    }
}

__global__ void k_zero_out(float4* out){
    int i = blockIdx.x*blockDim.x + threadIdx.x;
    if (i < 131072) out[i] = make_float4(0.f, 0.f, 0.f, 0.f);
}

// ---------------- launch ----------------
extern "C" void kernel_launch(void* const* d_in, const int* in_sizes, int n_in,
                              void* d_out, int out_size){
    const float* state = (const float*)d_in[0];
    const int*   lengths = (const int*)d_in[1];
    const float* Wih1 = (const float*)d_in[2];
    const float* Whh1 = (const float*)d_in[3];
    const float* bih1 = (const float*)d_in[4];
    const float* bhh1 = (const float*)d_in[5];
    const float* W1 = (const float*)d_in[6];
    const float* b1 = (const float*)d_in[7];
    const float* W2 = (const float*)d_in[8];
    const float* b2 = (const float*)d_in[9];
    const float* W3 = (const float*)d_in[10];
    const float* b3 = (const float*)d_in[11];
    const float* W4 = (const float*)d_in[12];
    const float* b4 = (const float*)d_in[13];
    const float* Wih2 = (const float*)d_in[14];
    const float* Whh2 = (const float*)d_in[15];
    const float* bih2 = (const float*)d_in[16];
    const float* bhh2 = (const float*)d_in[17];
    const float* Wpi = (const float*)d_in[18];
    const float* bpi = (const float*)d_in[19];
    float* out = (float*)d_out;
    (void)b4;

    k_sort<<<1, 256>>>(lengths);
    k_prep_gates<<<3072, 256>>>(Whh1, Wih2, Whh2);
    k_prep_small<<<68, 256>>>(Wih1, bih1, bhh1, bih2, bhh2);
    k_prep_T<<<7680, 256>>>(W1, W2, W3, W4);

    k_encoder<<<NG, 256>>>(state, lengths);

    k_rowgemm<<<NB/8, 256>>>(0, b1);
    k_rowgemm<<<NB/8, 256>>>(1, b2);
    k_rowgemm<<<NB/8, 256>>>(2, b3);
    k_rowgemm<<<NB/8, 256>>>(3, b4);
    k_rowgemm<<<NB/8, 256>>>(4, b1);   // layer 4 uses g_b2c internally

    k_zero_out<<<512, 256>>>((float4*)out);
    k_decoder<<<NG, 256>>>(lengths, Wpi, bpi, out);
}

// round 10
// speedup vs baseline: 1.1343x; 1.0090x over previous
#include <cuda_runtime.h>
#include <cstdint>

typedef unsigned long long u64;

#define NB 2048
#define VMAXD 128
#define NGRP 128          // 128 groups of 16
#define NCL 64            // 64 clusters x 2 CTAs = 128 CTAs (single wave on 152 SMs)

// ---------------- device scratch ----------------
__device__ __align__(16) float g_Wih1g[15*1024];
__device__ __align__(16) float g_Whh1g[256*1024];
__device__ __align__(16) float g_b1c[1024];
__device__ __align__(16) float g_Wih2g[256*1024];
__device__ __align__(16) float g_Whh2g[256*1024];
__device__ __align__(16) float g_b2c[1024];
__device__ __align__(16) float g_W1T[256*1024];
__device__ __align__(16) float g_W2T[1024*1024];
__device__ __align__(16) float g_W3T[1024*512];
__device__ __align__(16) float g_W4T[512*256];
__device__ __align__(16) float g_henc[NB*256];
__device__ __align__(16) float g_x1[NB*1024];
__device__ __align__(16) float g_x2[NB*1024];
__device__ __align__(16) float g_x3[NB*512];
__device__ __align__(16) float g_x4[NB*256];
__device__ __align__(16) float g_decin[NB*1024];
__device__ int   g_order[NB];

// ---------------- helpers ----------------
__device__ __forceinline__ u64 pk2(float x, float y){
    u64 r; asm("mov.b64 %0,{%1,%2};" : "=l"(r) : "f"(x), "f"(y)); return r;
}
__device__ __forceinline__ float2 upk2(u64 v){
    float2 r; asm("mov.b64 {%0,%1},%2;" : "=f"(r.x), "=f"(r.y) : "l"(v)); return r;
}
__device__ __forceinline__ void fma2(u64& d, u64 a, u64 b){
    asm("fma.rn.f32x2 %0,%1,%2,%0;" : "+l"(d) : "l"(a), "l"(b));
}
__device__ __forceinline__ float sigf(float x){ return 1.0f/(1.0f + __expf(-x)); }
__device__ __forceinline__ float tanhfast(float x){ return 2.0f*sigf(2.0f*x) - 1.0f; }

__device__ __forceinline__ uint32_t s2u(const void* p){
    uint32_t a;
    asm("{ .reg .u64 t; cvta.to.shared.u64 t,%1; cvt.u32.u64 %0,t; }" : "=r"(a) : "l"(p));
    return a;
}
__device__ __forceinline__ uint32_t mapa_u32(uint32_t a, uint32_t trank){
    uint32_t d; asm("mapa.shared::cluster.u32 %0,%1,%2;" : "=r"(d) : "r"(a), "r"(trank));
    return d;
}
__device__ __forceinline__ void st_cl_f4(uint32_t addr, float4 v){
    asm volatile("st.shared::cluster.v4.b32 [%0],{%1,%2,%3,%4};"
        :: "r"(addr), "r"(__float_as_uint(v.x)), "r"(__float_as_uint(v.y)),
           "r"(__float_as_uint(v.z)), "r"(__float_as_uint(v.w)) : "memory");
}
__device__ __forceinline__ void st_cl_f1(uint32_t addr, float v){
    asm volatile("st.shared::cluster.b32 [%0],%1;" :: "r"(addr), "r"(__float_as_uint(v)) : "memory");
}
#define CLUSTER_SYNC() do{ \
    asm volatile("barrier.cluster.arrive.aligned;" ::: "memory"); \
    asm volatile("barrier.cluster.wait.aligned;" ::: "memory"); }while(0)

// ---------------- weight prep ----------------
__global__ void k_prep_gates(const float* __restrict__ Whh1,
                             const float* __restrict__ Wih2,
                             const float* __restrict__ Whh2){
    int idx = blockIdx.x*blockDim.x + threadIdx.x;
    int m = idx >> 18;
    int r = idx & 262143;
    int k = r >> 10; int n = r & 1023; int jj = n >> 2, g = n & 3;
    int src = (g*256 + jj)*256 + k;
    if (m == 0)      g_Whh1g[r] = Whh1[src];
    else if (m == 1) g_Wih2g[r] = Wih2[src];
    else             g_Whh2g[r] = Whh2[src];
}

__global__ void k_prep_small(const float* __restrict__ Wih1,
                             const float* __restrict__ bih1, const float* __restrict__ bhh1,
                             const float* __restrict__ bih2, const float* __restrict__ bhh2){
    int idx = blockIdx.x*blockDim.x + threadIdx.x;
    if (idx < 15360){
        int k = idx >> 10, n = idx & 1023, jj = n >> 2, g = n & 3;
        g_Wih1g[idx] = Wih1[(g*256 + jj)*15 + k];
    } else if (idx < 16384){
        int n = idx - 15360; int jj = n >> 2, g = n & 3;
        g_b1c[n] = bih1[g*256 + jj] + bhh1[g*256 + jj];
    } else if (idx < 17408){
        int n = idx - 16384; int jj = n >> 2, g = n & 3;
        g_b2c[n] = bih2[g*256 + jj] + bhh2[g*256 + jj];
    }
}

__global__ void k_prep_T(const float* __restrict__ W1, const float* __restrict__ W2,
                         const float* __restrict__ W3, const float* __restrict__ W4){
    int idx = blockIdx.x*blockDim.x + threadIdx.x;
    if (idx < 262144){
        int k = idx >> 10, n = idx & 1023; g_W1T[idx] = W1[n*256 + k];
    } else if (idx < 1310720){
        int r = idx - 262144; int k = r >> 10, n = r & 1023; g_W2T[r] = W2[n*1024 + k];
    } else if (idx < 1835008){
        int r = idx - 1310720; int k = r >> 9, n = r & 511; g_W3T[r] = W3[n*1024 + k];
    } else if (idx < 1966080){
        int r = idx - 1835008; int k = r >> 8, n = r & 255; g_W4T[r] = W4[n*512 + k];
    }
}

// ---------------- single-launch length sort (descending) ----------------
__global__ void k_sort(const int* __restrict__ lengths){
    __shared__ int hist[129];
    __shared__ int start[129];
    int tid = threadIdx.x;
    if (tid < 129) hist[tid] = 0;
    __syncthreads();
    for (int b = tid; b < NB; b += 256) atomicAdd(&hist[lengths[b]], 1);
    __syncthreads();
    if (tid == 0){
        int run = 0;
        for (int l = 128; l >= 1; l--){ start[l] = run; run += hist[l]; }
    }
    __syncthreads();
    for (int b = tid; b < NB; b += 256){
        int l = lengths[b];
        int p = atomicAdd(&start[l], 1);
        g_order[p] = b;
    }
}

// ---------------- encoder: cluster-2 gate-split, GB=16, 2 groups per cluster ----------------
__global__ __launch_bounds__(512, 1) __cluster_dims__(2, 1, 1)
void k_encoder(const float* __restrict__ state, const int* __restrict__ lengths){
    __shared__ int s_b[16]; __shared__ int s_len[16]; __shared__ int s_maxs;
    __shared__ __align__(16) float h_s[2][256][16];   // mirrored full h, 64B rows
    __shared__ __align__(16) float x_s[2][15][16];
    const int tid  = threadIdx.x;
    const int rank = blockIdx.x & 1;
    const int cl   = blockIdx.x >> 1;

    const int u   = tid >> 2;            // local unit 0..127
    const int q   = tid & 3;             // batch quarter
    const int l0  = q << 2;              // my 4 batch lanes l0..l0+3
    const int ug  = rank*128 + u;
    const int col = ug << 2;

    const float4 bv = *(const float4*)(g_b1c + col);
    const u64 bi0 = pk2(bv.x,bv.x), bi1 = pk2(bv.y,bv.y), bi2 = pk2(bv.z,bv.z), bi3 = pk2(bv.w,bv.w);

    uint32_t ra0 = mapa_u32(s2u(&h_s[0][ug][l0]), rank ^ 1);
    uint32_t ra1 = mapa_u32(s2u(&h_s[1][ug][l0]), rank ^ 1);

    for (int pass = 0; pass < 2; pass++){
        const int grp = pass ? (NGRP - 1 - cl) : cl;

        if (tid < 16){ int b = g_order[grp*16 + tid]; s_b[tid] = b; s_len[tid] = lengths[b]; }
        for (int i = tid; i < 2*256*16; i += 512) ((float*)h_s)[i] = 0.0f;
        __syncthreads();
        if (tid == 0){
            int m = 1;
            #pragma unroll
            for (int i = 0; i < 16; i++) m = max(m, s_len[i]);
            s_maxs = m;
        }
        if (tid < 240){ int i = tid/15, e = tid - 15*i; x_s[0][e][i] = state[(s_b[i]*VMAXD + 0)*15 + e]; }
        __syncthreads();
        const int T = s_maxs;
        int sl[4];
        #pragma unroll
        for (int l = 0; l < 4; l++) sl[l] = s_len[l0 + l];

        float cr[4], hreg[4];
        #pragma unroll
        for (int l = 0; l < 4; l++){ cr[l] = 0.0f; hreg[l] = 0.0f; }

        CLUSTER_SYNC();   // both CTAs zeroed h before any DSMEM store lands

        for (int t = 0; t < T; t++){
            const int cb = t & 1, nb = cb ^ 1;
            u64 acc[4][2];
            acc[0][0]=bi0; acc[0][1]=bi0; acc[1][0]=bi1; acc[1][1]=bi1;
            acc[2][0]=bi2; acc[2][1]=bi2; acc[3][0]=bi3; acc[3][1]=bi3;

            #pragma unroll
            for (int k = 0; k < 15; k++){
                float4 w = *(const float4*)(g_Wih1g + (k<<10) + col);
                u64 w0 = pk2(w.x,w.x), w1 = pk2(w.y,w.y), w2 = pk2(w.z,w.z), w3 = pk2(w.w,w.w);
                const float* xr = &x_s[cb][k][l0];
                u64 x0 = *(const u64*)(xr), x1 = *(const u64*)(xr + 2);
                fma2(acc[0][0], w0, x0); fma2(acc[0][1], w0, x1);
                fma2(acc[1][0], w1, x0); fma2(acc[1][1], w1, x1);
                fma2(acc[2][0], w2, x0); fma2(acc[2][1], w2, x1);
                fma2(acc[3][0], w3, x0); fma2(acc[3][1], w3, x1);
            }
            #pragma unroll 4
            for (int k = 0; k < 256; k++){
                float4 w = *(const float4*)(g_Whh1g + (k<<10) + col);
                u64 w0 = pk2(w.x,w.x), w1 = pk2(w.y,w.y), w2 = pk2(w.z,w.z), w3 = pk2(w.w,w.w);
                const float* hr = &h_s[cb][k][l0];
                u64 h0 = *(const u64*)(hr), h1 = *(const u64*)(hr + 2);
                fma2(acc[0][0], w0, h0); fma2(acc[0][1], w0, h1);
                fma2(acc[1][0], w1, h0); fma2(acc[1][1], w1, h1);
                fma2(acc[2][0], w2, h0); fma2(acc[2][1], w2, h1);
                fma2(acc[3][0], w3, h0); fma2(acc[3][1], w3, h1);
            }

            if (tid < 240 && t + 1 < T){
                int i = tid/15, e = tid - 15*i;
                x_s[nb][e][i] = state[(s_b[i]*VMAXD + (t+1))*15 + e];
            }

            #pragma unroll
            for (int p = 0; p < 2; p++){
                float2 gi = upk2(acc[0][p]), gf = upk2(acc[1][p]);
                float2 gg = upk2(acc[2][p]), go = upk2(acc[3][p]);
                int l = 2*p;
                if (t < sl[l]){
                    float cn = sigf(gf.x)*cr[l] + sigf(gi.x)*tanhfast(gg.x);
                    cr[l] = cn; hreg[l] = sigf(go.x)*tanhfast(cn);
                }
                l++;
                if (t < sl[l]){
                    float cn = sigf(gf.y)*cr[l] + sigf(gi.y)*tanhfast(gg.y);
                    cr[l] = cn; hreg[l] = sigf(go.y)*tanhfast(cn);
                }
            }

            float4 hv = make_float4(hreg[0], hreg[1], hreg[2], hreg[3]);
            *(float4*)(&h_s[nb][ug][l0]) = hv;
            st_cl_f4(nb ? ra1 : ra0, hv);

            CLUSTER_SYNC();
        }

        #pragma unroll
        for (int l = 0; l < 4; l++) g_henc[s_b[l0 + l]*256 + ug] = hreg[l];
        // both CTAs exit the step loop at the same T (same group) -> safe to re-init
    }
}

// ---------------- row GEMM: C = act(A @ W^T + bias), 8 rows / CTA ----------------
__global__ __launch_bounds__(256, 2)
void k_rowgemm(int layer, const float* __restrict__ bias_in){
    const float *A, *W; float* C; int K, N; bool dorelu = true; const float* bias = bias_in;
    if      (layer == 0){ A = g_henc; W = g_W1T;   C = g_x1;    K = 256;  N = 1024; }
    else if (layer == 1){ A = g_x1;   W = g_W2T;   C = g_x2;    K = 1024; N = 1024; }
    else if (layer == 2){ A = g_x2;   W = g_W3T;   C = g_x3;    K = 1024; N = 512;  }
    else if (layer == 3){ A = g_x3;   W = g_W4T;   C = g_x4;    K = 512;  N = 256;  }
    else               { A = g_x4;   W = g_Wih2g; C = g_decin; K = 256;  N = 1024; dorelu = false; bias = g_b2c; }

    __shared__ __align__(16) float A_s[1024*8];
    const int tid = threadIdx.x;
    const int row0 = blockIdx.x * 8;
    for (int idx = tid; idx < 8*K; idx += 256){
        int i = idx / K, k = idx - i*K;
        A_s[k*8 + i] = A[(row0 + i)*K + k];
    }
    __syncthreads();

    const int j = tid;
    if (4*j < N){
        float4 bvv = *(const float4*)(bias + 4*j);
        u64 acc[4][4];
        u64 b0 = pk2(bvv.x,bvv.x), b1 = pk2(bvv.y,bvv.y), b2 = pk2(bvv.z,bvv.z), b3 = pk2(bvv.w,bvv.w);
        #pragma unroll
        for (int bp = 0; bp < 4; bp++){ acc[bp][0]=b0; acc[bp][1]=b1; acc[bp][2]=b2; acc[bp][3]=b3; }

        #pragma unroll 4
        for (int k = 0; k < K; k++){
            float4 w = *(const float4*)(W + k*N + 4*j);
            u64 w0 = pk2(w.x,w.x), w1 = pk2(w.y,w.y), w2 = pk2(w.z,w.z), w3 = pk2(w.w,w.w);
            const float* ar = A_s + k*8;
            #pragma unroll
            for (int bp = 0; bp < 4; bp++){
                u64 ap = *(const u64*)(ar + 2*bp);
                fma2(acc[bp][0], w0, ap); fma2(acc[bp][1], w1, ap);
                fma2(acc[bp][2], w2, ap); fma2(acc[bp][3], w3, ap);
            }
        }
        #pragma unroll
        for (int bp = 0; bp < 4; bp++){
            float2 v0 = upk2(acc[bp][0]), v1 = upk2(acc[bp][1]);
            float2 v2 = upk2(acc[bp][2]), v3 = upk2(acc[bp][3]);
            float4 r0 = make_float4(v0.x, v1.x, v2.x, v3.x);
            float4 r1 = make_float4(v0.y, v1.y, v2.y, v3.y);
            if (dorelu){
                r0.x = fmaxf(r0.x,0.f); r0.y = fmaxf(r0.y,0.f); r0.z = fmaxf(r0.z,0.f); r0.w = fmaxf(r0.w,0.f);
                r1.x = fmaxf(r1.x,0.f); r1.y = fmaxf(r1.y,0.f); r1.z = fmaxf(r1.z,0.f); r1.w = fmaxf(r1.w,0.f);
            }
            *(float4*)(C + (row0 + 2*bp    )*N + 4*j) = r0;
            *(float4*)(C + (row0 + 2*bp + 1)*N + 4*j) = r1;
        }
    }
}

// ---------------- decoder: cluster-2 gate-split, GB=16, 2 groups per cluster ----------------
__global__ __launch_bounds__(512, 1) __cluster_dims__(2, 1, 1)
void k_decoder(const int* __restrict__ lengths, const float* __restrict__ Wpi,
               const float* __restrict__ bpi, float* __restrict__ out){
    __shared__ int s_b[16]; __shared__ int s_len[16]; __shared__ int s_maxs;
    __shared__ __align__(16) float h_s[2][256][16];
    __shared__ __align__(16) float c_s[128][16];     // my units' c
    __shared__ float wpi_s[512];
    __shared__ float p_s[2][2][32];                  // [t&1][rank][b*2+a]
    __shared__ float bpi_s[2];
    const int tid  = threadIdx.x;
    const int rank = blockIdx.x & 1;
    const int cl   = blockIdx.x >> 1;

    const int u   = tid >> 2;
    const int q   = tid & 3;
    const int l0  = q << 2;
    const int ug  = rank*128 + u;
    const int col = ug << 2;

    if (tid < 2) bpi_s[tid] = bpi[tid];
    if (tid < 512 && tid >= 0){ if (tid < 512) {} }
    for (int i = tid; i < 512; i += 512) wpi_s[i] = Wpi[i];

    uint32_t ra0 = mapa_u32(s2u(&h_s[0][ug][l0]), rank ^ 1);
    uint32_t ra1 = mapa_u32(s2u(&h_s[1][ug][l0]), rank ^ 1);

    for (int pass = 0; pass < 2; pass++){
        const int grp = pass ? (NGRP - 1 - cl) : cl;

        if (tid < 16){ int b = g_order[grp*16 + tid]; s_b[tid] = b; s_len[tid] = lengths[b]; }
        for (int i = tid; i < 2*256*16; i += 512) ((float*)h_s)[i] = 0.0f;
        __syncthreads();
        if (tid == 0){
            int m = 1;
            #pragma unroll
            for (int i = 0; i < 16; i++) m = max(m, s_len[i]);
            s_maxs = m;
        }
        __syncthreads();
        const int T = s_maxs;

        // decoder constant input gates in registers: din[g][p] packs lanes (l0+2p, l0+2p+1)
        u64 din[4][2];
        #pragma unroll
        for (int g = 0; g < 4; g++){
            float v[4];
            #pragma unroll
            for (int j = 0; j < 4; j++) v[j] = g_decin[s_b[l0 + j]*1024 + col + g];
            din[g][0] = pk2(v[0], v[1]); din[g][1] = pk2(v[2], v[3]);
        }
        float cr[4];
        #pragma unroll
        for (int l = 0; l < 4; l++) cr[l] = 0.0f;

        CLUSTER_SYNC();

        for (int t = 0; t < T; t++){
            const int cb = t & 1, nb = cb ^ 1;

            // write previous step's output (p_s parity-buffered)
            if (t > 0 && tid < 32){
                int b = tid >> 1, a = tid & 1;
                if (t - 1 < s_len[b]){
                    float v = tanhfast(p_s[nb][0][tid] + p_s[nb][1][tid] + bpi_s[a]);
                    out[(s_b[b]*VMAXD + (t-1))*2 + a] = v;
                }
            }

            u64 acc[4][2];
            acc[0][0]=din[0][0]; acc[0][1]=din[0][1];
            acc[1][0]=din[1][0]; acc[1][1]=din[1][1];
            acc[2][0]=din[2][0]; acc[2][1]=din[2][1];
            acc[3][0]=din[3][0]; acc[3][1]=din[3][1];

            #pragma unroll 4
            for (int k = 0; k < 256; k++){
                float4 w = *(const float4*)(g_Whh2g + (k<<10) + col);
                u64 w0 = pk2(w.x,w.x), w1 = pk2(w.y,w.y), w2 = pk2(w.z,w.z), w3 = pk2(w.w,w.w);
                const float* hr = &h_s[cb][k][l0];
                u64 h0 = *(const u64*)(hr), h1 = *(const u64*)(hr + 2);
                fma2(acc[0][0], w0, h0); fma2(acc[0][1], w0, h1);
                fma2(acc[1][0], w1, h0); fma2(acc[1][1], w1, h1);
                fma2(acc[2][0], w2, h0); fma2(acc[2][1], w2, h1);
                fma2(acc[3][0], w3, h0); fma2(acc[3][1], w3, h1);
            }

            float hreg[4];
            #pragma unroll
            for (int p = 0; p < 2; p++){
                float2 gi = upk2(acc[0][p]), gf = upk2(acc[1][p]);
                float2 gg = upk2(acc[2][p]), go = upk2(acc[3][p]);
                int l = 2*p;
                {
                    float cn = sigf(gf.x)*cr[l] + sigf(gi.x)*tanhfast(gg.x);
                    cr[l] = cn; hreg[l] = sigf(go.x)*tanhfast(cn);
                }
                l++;
                {
                    float cn = sigf(gf.y)*cr[l] + sigf(gi.y)*tanhfast(gg.y);
                    cr[l] = cn; hreg[l] = sigf(go.y)*tanhfast(cn);
                }
            }

            float4 hv = make_float4(hreg[0], hreg[1], hreg[2], hreg[3]);
            *(float4*)(&h_s[nb][ug][l0]) = hv;
            st_cl_f4(nb ? ra1 : ra0, hv);
            *(float4*)(&c_s[u][l0]) = make_float4(cr[0], cr[1], cr[2], cr[3]);

            __syncthreads();   // c_s complete before reduction

            // policy partials over MY 128 units: 32 dots (16 b x 2 a), 8 lanes each
            if (tid < 256){
                int p = tid >> 3, kk = tid & 7;
                int b = p >> 1, a = p & 1;
                const float* wr = wpi_s + a*256 + rank*128;
                float sum = 0.0f;
                #pragma unroll
                for (int qq = 0; qq < 16; qq++){
                    int uu = kk + 8*qq;
                    sum += c_s[uu][b] * wr[uu];
                }
                sum += __shfl_xor_sync(0xffffffffu, sum, 4);
                sum += __shfl_xor_sync(0xffffffffu, sum, 2);
                sum += __shfl_xor_sync(0xffffffffu, sum, 1);
                if (kk == 0){
                    p_s[cb][rank][p] = sum;
                    st_cl_f1(mapa_u32(s2u(&p_s[cb][rank][p]), rank ^ 1), sum);
                }
            }

            CLUSTER_SYNC();
        }

        // final step's output
        if (tid < 32){
            int b = tid >> 1, a = tid & 1;
            if (T - 1 < s_len[b]){
                int pb = (T - 1) & 1;
                float v = tanhfast(p_s[pb][0][tid] + p_s[pb][1][tid] + bpi_s[a]);
                out[(s_b[b]*VMAXD + (T-1))*2 + a] = v;
            }
        }
        CLUSTER_SYNC();  // peers done reading p_s/h before re-init
    }
}

__global__ void k_zero_out(float4* out){
    int i = blockIdx.x*blockDim.x + threadIdx.x;
    if (i < 131072) out[i] = make_float4(0.f, 0.f, 0.f, 0.f);
}

// ---------------- launch ----------------
extern "C" void kernel_launch(void* const* d_in, const int* in_sizes, int n_in,
                              void* d_out, int out_size){
    const float* state = (const float*)d_in[0];
    const int*   lengths = (const int*)d_in[1];
    const float* Wih1 = (const float*)d_in[2];
    const float* Whh1 = (const float*)d_in[3];
    const float* bih1 = (const float*)d_in[4];
    const float* bhh1 = (const float*)d_in[5];
    const float* W1 = (const float*)d_in[6];
    const float* b1 = (const float*)d_in[7];
    const float* W2 = (const float*)d_in[8];
    const float* b2 = (const float*)d_in[9];
    const float* W3 = (const float*)d_in[10];
    const float* b3 = (const float*)d_in[11];
    const float* W4 = (const float*)d_in[12];
    const float* b4 = (const float*)d_in[13];
    const float* Wih2 = (const float*)d_in[14];
    const float* Whh2 = (const float*)d_in[15];
    const float* bih2 = (const float*)d_in[16];
    const float* bhh2 = (const float*)d_in[17];
    const float* Wpi = (const float*)d_in[18];
    const float* bpi = (const float*)d_in[19];
    float* out = (float*)d_out;
    (void)b4;

    k_sort<<<1, 256>>>(lengths);
    k_prep_gates<<<3072, 256>>>(Whh1, Wih2, Whh2);
    k_prep_small<<<68, 256>>>(Wih1, bih1, bhh1, bih2, bhh2);
    k_prep_T<<<7680, 256>>>(W1, W2, W3, W4);

    k_encoder<<<2*NCL, 512>>>(state, lengths);

    k_rowgemm<<<NB/8, 256>>>(0, b1);
    k_rowgemm<<<NB/8, 256>>>(1, b2);
    k_rowgemm<<<NB/8, 256>>>(2, b3);
    k_rowgemm<<<NB/8, 256>>>(3, b4);
    k_rowgemm<<<NB/8, 256>>>(4, b1);   // layer 4 uses g_b2c internally

    k_zero_out<<<512, 256>>>((float4*)out);
    k_decoder<<<2*NCL, 512>>>(lengths, Wpi, bpi, out);
}